// round 10
// baseline (speedup 1.0000x reference)
#include <cuda_runtime.h>
#include <cuda_bf16.h>
#include <cuda_fp8.h>
#include <cstdint>
#include <cstddef>

#define TT 8192
#define HH 4096

// ------------------------- device scratch (no allocs allowed) ---------------
__device__ float          g_resid[(size_t)TT * HH];        // 128 MB fp32 residual
__device__ __nv_bfloat16  g_yq[(size_t)TT * HH];           // 64 MB quantized activations
__device__ __nv_bfloat16  g_wq[(size_t)3 * HH * HH];       // 96 MB quantized weights

// ------------------------- small helpers ------------------------------------
static __device__ __forceinline__ uint32_t smem_u32(const void* p) {
    uint32_t a;
    asm("{ .reg .u64 t; cvta.to.shared.u64 t, %1; cvt.u32.u64 %0, t; }" : "=r"(a) : "l"(p));
    return a;
}
static __device__ __forceinline__ uint32_t sw128(uint32_t x) { return x ^ ((x >> 3) & 0x70); }

static __device__ __forceinline__ void cp_async16(uint32_t dst, const void* src) {
    asm volatile("cp.async.cg.shared.global [%0], [%1], 16;" :: "r"(dst), "l"(src) : "memory");
}

#define LDSM4(r, addr) \
    asm volatile("ldmatrix.sync.aligned.m8n8.x4.shared.b16 {%0,%1,%2,%3}, [%4];" \
        : "=r"((r)[0]), "=r"((r)[1]), "=r"((r)[2]), "=r"((r)[3]) : "r"(addr))

#define MMA16816(c, a, b0, b1) \
    asm volatile("mma.sync.aligned.m16n8k16.row.col.f32.bf16.bf16.f32 " \
        "{%0,%1,%2,%3}, {%4,%5,%6,%7}, {%8,%9}, {%0,%1,%2,%3};" \
        : "+f"((c)[0]), "+f"((c)[1]), "+f"((c)[2]), "+f"((c)[3]) \
        : "r"((a)[0]), "r"((a)[1]), "r"((a)[2]), "r"((a)[3]), "r"(b0), "r"(b1))

// ------------------------- NVFP4 quantization (bit-exact vs reference) ------
static __device__ __forceinline__ float e4m3_rt(float x) {
    __nv_fp8_e4m3 v(x);            // RN, satfinite — matches ml_dtypes in-range
    return float(v);
}
static __device__ __forceinline__ uint32_t pack_bf2(float a, float b) {
    __nv_bfloat162 h = __floats2bfloat162_rn(a, b);
    return *reinterpret_cast<uint32_t*>(&h);
}
// x[16] fp32 -> 8 packed bf16x2 of (q * s8)  (== dequant * gscale, exact in bf16)
static __device__ __forceinline__ void quant16(const float* x, float g, uint32_t* pk) {
    float amax = 0.f;
#pragma unroll
    for (int i = 0; i < 16; i++) amax = fmaxf(amax, fabsf(x[i]));
    float s8 = e4m3_rt(__fdiv_rn(__fmul_rn(amax, g), 6.0f));
    if (s8 > 0.f) {
        float o[16];
#pragma unroll
        for (int i = 0; i < 16; i++) {
            float v = __fdiv_rn(__fmul_rn(x[i], g), s8);
            float a = fminf(fabsf(v), 6.0f);
            float gr;
            if (a < 1.25f)      gr = (a < 0.25f) ? 0.0f : ((a < 0.75f) ? 0.5f : 1.0f);
            else if (a < 2.5f)  gr = (a < 1.75f) ? 1.5f : 2.0f;
            else                gr = (a < 3.5f) ? 3.0f : ((a < 5.0f) ? 4.0f : 6.0f);
            o[i] = __fmul_rn(copysignf(gr, v), s8);
        }
#pragma unroll
        for (int i = 0; i < 8; i++) pk[i] = pack_bf2(o[2 * i], o[2 * i + 1]);
    } else {
#pragma unroll
        for (int i = 0; i < 8; i++) pk[i] = 0u;
    }
}

// ------------------------- fused norm bodies ---------------------------------
// MODE 0: relu(hidden) -> resid, rmsnorm, quant -> g_yq
// MODE 1: rmsnorm(g_resid), quant -> g_yq
// MODE 2: rmsnorm(g_resid) -> out (fp32)
template <int MODE>
static __device__ __forceinline__ void norm_body(int row,
                                                 const float* __restrict__ hid,
                                                 const float* __restrict__ nw,
                                                 const float* __restrict__ ag, int agi,
                                                 float* __restrict__ out) {
    __shared__ float red[8];
    int t = threadIdx.x, lane = t & 31, wid = t >> 5;
    size_t base = (size_t)row * HH + t * 16;
    const float* src = (MODE == 0) ? (hid + base) : (g_resid + base);

    float x[16];
    const float4* s4 = reinterpret_cast<const float4*>(src);
#pragma unroll
    for (int i = 0; i < 4; i++) {
        float4 v = s4[i];
        x[4 * i] = v.x; x[4 * i + 1] = v.y; x[4 * i + 2] = v.z; x[4 * i + 3] = v.w;
    }
    if (MODE == 0) {
#pragma unroll
        for (int i = 0; i < 16; i++) x[i] = fmaxf(x[i], 0.0f);
        float4* r4 = reinterpret_cast<float4*>(g_resid + base);
#pragma unroll
        for (int i = 0; i < 4; i++)
            r4[i] = make_float4(x[4 * i], x[4 * i + 1], x[4 * i + 2], x[4 * i + 3]);
    }
    float ss = 0.f;
#pragma unroll
    for (int i = 0; i < 16; i++) ss += x[i] * x[i];
#pragma unroll
    for (int o = 16; o; o >>= 1) ss += __shfl_xor_sync(0xffffffffu, ss, o);
    if (lane == 0) red[wid] = ss;
    __syncthreads();
    if (wid == 0) {
        float v = (lane < 8) ? red[lane] : 0.f;
#pragma unroll
        for (int o = 4; o; o >>= 1) v += __shfl_xor_sync(0xffffffffu, v, o);
        if (lane == 0) red[0] = v;
    }
    __syncthreads();
    float rs = __frsqrt_rn(red[0] * (1.0f / 4096.0f) + 1e-6f);

    float y[16];
    const float* nwp = nw + t * 16;
#pragma unroll
    for (int i = 0; i < 16; i++) y[i] = __fmul_rn(__fmul_rn(x[i], rs), nwp[i]);

    if (MODE == 2) {
        float4* o4 = reinterpret_cast<float4*>(out + base);
#pragma unroll
        for (int i = 0; i < 4; i++)
            o4[i] = make_float4(y[4 * i], y[4 * i + 1], y[4 * i + 2], y[4 * i + 3]);
    } else {
        float g = ag[agi];
        uint32_t pk[8];
        quant16(y, g, pk);
        uint4* q4 = reinterpret_cast<uint4*>(g_yq + base);
        q4[0] = make_uint4(pk[0], pk[1], pk[2], pk[3]);
        q4[1] = make_uint4(pk[4], pk[5], pk[6], pk[7]);
    }
}

template <int MODE>
__global__ void __launch_bounds__(256) k_norm(const float* __restrict__ hid,
                                              const float* __restrict__ nw,
                                              const float* __restrict__ ag, int agi,
                                              float* __restrict__ out) {
    norm_body<MODE>(blockIdx.x, hid, nw, ag, agi, out);
}

// ---------------- fused init: weight quant (blocks 0..12287) + norm0 --------
#define WQ_BLOCKS 12288
__global__ void __launch_bounds__(256) k_init(const float* __restrict__ w,
                                              const float* __restrict__ wg,
                                              const float* __restrict__ hid,
                                              const float* __restrict__ nw,
                                              const float* __restrict__ ag) {
    if (blockIdx.x < WQ_BLOCKS) {
        size_t blk  = (size_t)blockIdx.x * 256 + threadIdx.x;
        size_t base = blk * 16;
        int layer   = (int)(blk >> 20);
        float g = wg[layer];
        float x[16];
        const float4* s4 = reinterpret_cast<const float4*>(w + base);
#pragma unroll
        for (int i = 0; i < 4; i++) {
            float4 v = s4[i];
            x[4 * i] = v.x; x[4 * i + 1] = v.y; x[4 * i + 2] = v.z; x[4 * i + 3] = v.w;
        }
        uint32_t pk[8];
        quant16(x, g, pk);
        uint4* q4 = reinterpret_cast<uint4*>(g_wq + base);
        q4[0] = make_uint4(pk[0], pk[1], pk[2], pk[3]);
        q4[1] = make_uint4(pk[4], pk[5], pk[6], pk[7]);
    } else {
        norm_body<0>(blockIdx.x - WQ_BLOCKS, hid, nw, ag, 0, nullptr);
    }
}

// ------------------------- mma.sync GEMM -------------------------------------
// z = yq @ wq^T, CTA tile 128x128, BK=64, 256 threads / 8 warps (2m x 4n),
// warp tile 64x32. 3 stages x 32KB = 96KB smem -> 2 CTAs/SM.
// Register-level fragment double-buffering: LDSM for ks+1 issues before the
// MMA batch of ks, keeping the tensor pipe fed through LDSM latency windows.
// Epilogue: g_resid += z * alpha.
#define GSTAGE 32768              // A 16KB + B 16KB
#define GSTAGES 3
#define GSMEM_TOTAL (GSTAGE * GSTAGES)   // 96 KB

static __device__ __forceinline__ void load_stage(uint32_t sb, int tid, int M0, int N0,
                                                  const __nv_bfloat16* __restrict__ Bp,
                                                  int s, int j) {
    uint32_t sa  = sb + (uint32_t)s * GSTAGE;
    uint32_t sbb = sa + 16384u;
    int k0 = j * 64;
    // A and B: each 128 rows x 128B (1024 x 16B chunks)
#pragma unroll
    for (int it = 0; it < 4; ++it) {
        int c = tid + it * 256;
        int row = c >> 3, kc = c & 7;
        uint32_t rel = sw128((uint32_t)(row * 128 + kc * 16));
        cp_async16(sa + rel,  g_yq + (size_t)(M0 + row) * HH + k0 + kc * 8);
        cp_async16(sbb + rel, Bp   + (size_t)(N0 + row) * HH + k0 + kc * 8);
    }
}

__global__ void __launch_bounds__(256, 2)
k_gemm(const float* __restrict__ ag, const float* __restrict__ wg, int layer) {
    extern __shared__ char smem[];
    uint32_t sb = smem_u32(smem);
    const int tid = threadIdx.x, wid = tid >> 5, lane = tid & 31;
    const int M0 = blockIdx.y * 128, N0 = blockIdx.x * 128;
    const int wm = wid & 1, wn = wid >> 1;      // 2 x 4 warp grid
    const __nv_bfloat16* Bp = g_wq + (size_t)layer * HH * HH;

    float acc[4][4][4];
#pragma unroll
    for (int i = 0; i < 4; i++)
#pragma unroll
        for (int j = 0; j < 4; j++)
#pragma unroll
            for (int k = 0; k < 4; k++) acc[i][j][k] = 0.f;

    // lane-invariant ldmatrix address pieces
    const int arow = wm * 64 + (lane & 7) + ((lane >> 3) & 1) * 8;   // + mf*16
    const int akh  = (lane >> 4) * 8;                                 // k half (0/8)
    const int brow = wn * 32 + (lane & 7) + (lane >> 4) * 8;          // + p*16
    const int bkh  = ((lane >> 3) & 1) * 8;

    // prologue: stages 0,1
#pragma unroll
    for (int j = 0; j < 2; j++) {
        load_stage(sb, tid, M0, N0, Bp, j, j);
        asm volatile("cp.async.commit_group;" ::: "memory");
    }

    // fragment double buffers
    uint32_t afr[2][4][4], bfr[2][2][4];

    // uniform: one commit per iteration (empty in tail) so wait_group 1
    // always means "stage kk's group is complete".
    for (int kk = 0; kk < 64; ++kk) {
        asm volatile("cp.async.wait_group 1;" ::: "memory");
        __syncthreads();

        int jn = kk + 2;
        if (jn < 64) load_stage(sb, tid, M0, N0, Bp, jn % GSTAGES, jn);
        asm volatile("cp.async.commit_group;" ::: "memory");

        uint32_t Ab = sb + (uint32_t)(kk % GSTAGES) * GSTAGE;
        uint32_t Bb = Ab + 16384u;

        // prime fragments for ks=0
#pragma unroll
        for (int mf = 0; mf < 4; mf++)
            LDSM4(afr[0][mf], Ab + sw128((uint32_t)((arow + mf * 16) * 128 + akh * 2)));
#pragma unroll
        for (int p = 0; p < 2; p++)
            LDSM4(bfr[0][p], Bb + sw128((uint32_t)((brow + p * 16) * 128 + bkh * 2)));

#pragma unroll
        for (int ks = 0; ks < 4; ks++) {
            int cur = ks & 1, nxt = cur ^ 1;
            if (ks < 3) {
                int kb = (ks + 1) * 16;
#pragma unroll
                for (int mf = 0; mf < 4; mf++)
                    LDSM4(afr[nxt][mf], Ab + sw128((uint32_t)((arow + mf * 16) * 128 + (kb + akh) * 2)));
#pragma unroll
                for (int p = 0; p < 2; p++)
                    LDSM4(bfr[nxt][p], Bb + sw128((uint32_t)((brow + p * 16) * 128 + (kb + bkh) * 2)));
            }
#pragma unroll
            for (int mf = 0; mf < 4; mf++) {
#pragma unroll
                for (int nf = 0; nf < 4; nf++)
                    MMA16816(acc[mf][nf], afr[cur][mf],
                             bfr[cur][nf >> 1][(nf & 1) * 2], bfr[cur][nf >> 1][(nf & 1) * 2 + 1]);
            }
        }
    }

    // ---------------- epilogue: g_resid += acc * alpha ----------------------
    float alpha = __fdiv_rn(1.0f, __fmul_rn(ag[layer], wg[layer]));
    int qr = lane >> 2, qc = lane & 3;
#pragma unroll
    for (int mf = 0; mf < 4; mf++) {
#pragma unroll
        for (int nf = 0; nf < 4; nf++) {
            int m0 = M0 + wm * 64 + mf * 16 + qr;
            int n0 = N0 + wn * 32 + nf * 8 + 2 * qc;
            float2* p0 = reinterpret_cast<float2*>(&g_resid[(size_t)m0 * HH + n0]);
            float2 v0 = *p0;
            v0.x += __fmul_rn(acc[mf][nf][0], alpha);
            v0.y += __fmul_rn(acc[mf][nf][1], alpha);
            *p0 = v0;
            float2* p1 = reinterpret_cast<float2*>(&g_resid[(size_t)(m0 + 8) * HH + n0]);
            float2 v1 = *p1;
            v1.x += __fmul_rn(acc[mf][nf][2], alpha);
            v1.y += __fmul_rn(acc[mf][nf][3], alpha);
            *p1 = v1;
        }
    }
}

// ------------------------- launcher ------------------------------------------
extern "C" void kernel_launch(void* const* d_in, const int* in_sizes, int n_in,
                              void* d_out, int out_size) {
    const float* hid = (const float*)d_in[0];   // [8192, 4096]
    const float* nw  = (const float*)d_in[1];   // [4, 4096]
    const float* w   = (const float*)d_in[2];   // [3, 4096, 4096]
    const float* ag  = (const float*)d_in[3];   // [3]
    const float* wg  = (const float*)d_in[4];   // [3]
    float* out = (float*)d_out;

    cudaFuncSetAttribute(k_gemm, cudaFuncAttributeMaxDynamicSharedMemorySize, GSMEM_TOTAL);

    // fused: weight quant + relu/resid/rmsnorm/quant(ag[0])
    k_init<<<WQ_BLOCKS + TT, 256>>>(w, wg, hid, nw, ag);

    dim3 ggrid(HH / 128, TT / 128);  // (32, 64): N fastest for B reuse in L2
    for (int i = 0; i < 3; i++) {
        k_gemm<<<ggrid, 256, GSMEM_TOTAL>>>(ag, wg, i);
        if (i < 2)
            k_norm<1><<<TT, 256>>>(nullptr, nw + (size_t)(i + 1) * HH, ag, i + 1, nullptr);
    }
    k_norm<2><<<TT, 256>>>(nullptr, nw + (size_t)3 * HH, ag, 0, out);
}

// round 12
// speedup vs baseline: 1.0098x; 1.0098x over previous
#include <cuda_runtime.h>
#include <cuda_bf16.h>
#include <cuda_fp8.h>
#include <cstdint>
#include <cstddef>

#define TT 8192
#define HH 4096

// ------------------------- device scratch (no allocs allowed) ---------------
__device__ float          g_resid[(size_t)TT * HH];        // 128 MB fp32 residual
__device__ __nv_bfloat16  g_yq[(size_t)TT * HH];           // 64 MB quantized activations
__device__ __nv_bfloat16  g_wq[(size_t)3 * HH * HH];       // 96 MB quantized weights

// ------------------------- small helpers ------------------------------------
static __device__ __forceinline__ uint32_t smem_u32(const void* p) {
    uint32_t a;
    asm("{ .reg .u64 t; cvta.to.shared.u64 t, %1; cvt.u32.u64 %0, t; }" : "=r"(a) : "l"(p));
    return a;
}
static __device__ __forceinline__ uint32_t sw128(uint32_t x) { return x ^ ((x >> 3) & 0x70); }

static __device__ __forceinline__ void cp_async16(uint32_t dst, const void* src) {
    asm volatile("cp.async.cg.shared.global [%0], [%1], 16;" :: "r"(dst), "l"(src) : "memory");
}

#define LDSM4(r, addr) \
    asm volatile("ldmatrix.sync.aligned.m8n8.x4.shared.b16 {%0,%1,%2,%3}, [%4];" \
        : "=r"((r)[0]), "=r"((r)[1]), "=r"((r)[2]), "=r"((r)[3]) : "r"(addr))

#define MMA16816(c, a, b0, b1) \
    asm volatile("mma.sync.aligned.m16n8k16.row.col.f32.bf16.bf16.f32 " \
        "{%0,%1,%2,%3}, {%4,%5,%6,%7}, {%8,%9}, {%0,%1,%2,%3};" \
        : "+f"((c)[0]), "+f"((c)[1]), "+f"((c)[2]), "+f"((c)[3]) \
        : "r"((a)[0]), "r"((a)[1]), "r"((a)[2]), "r"((a)[3]), "r"(b0), "r"(b1))

// ------------------------- NVFP4 quantization --------------------------------
static __device__ __forceinline__ float e4m3_rt(float x) {
    __nv_fp8_e4m3 v(x);            // RN, satfinite — matches ml_dtypes in-range
    return float(v);
}
static __device__ __forceinline__ uint32_t pack_bf2(float a, float b) {
    __nv_bfloat162 h = __floats2bfloat162_rn(a, b);
    return *reinterpret_cast<uint32_t*>(&h);
}
// x[16] fp32 -> 8 packed bf16x2 of (q * s8)  (== dequant * gscale, exact in bf16)
// One true divide per block (inv = 1/s8), then multiplies: <=1 ulp vs (x*g)/s8.
static __device__ __forceinline__ void quant16(const float* x, float g, uint32_t* pk) {
    float amax = 0.f;
#pragma unroll
    for (int i = 0; i < 16; i++) amax = fmaxf(amax, fabsf(x[i]));
    float s8 = e4m3_rt(__fdiv_rn(__fmul_rn(amax, g), 6.0f));
    if (s8 > 0.f) {
        float inv = __fdiv_rn(1.0f, s8);
        float o[16];
#pragma unroll
        for (int i = 0; i < 16; i++) {
            float v = __fmul_rn(__fmul_rn(x[i], g), inv);
            float a = fminf(fabsf(v), 6.0f);
            float gr;
            if (a < 1.25f)      gr = (a < 0.25f) ? 0.0f : ((a < 0.75f) ? 0.5f : 1.0f);
            else if (a < 2.5f)  gr = (a < 1.75f) ? 1.5f : 2.0f;
            else                gr = (a < 3.5f) ? 3.0f : ((a < 5.0f) ? 4.0f : 6.0f);
            o[i] = __fmul_rn(copysignf(gr, v), s8);
        }
#pragma unroll
        for (int i = 0; i < 8; i++) pk[i] = pack_bf2(o[2 * i], o[2 * i + 1]);
    } else {
#pragma unroll
        for (int i = 0; i < 8; i++) pk[i] = 0u;
    }
}

// ------------------------- fused norm bodies ---------------------------------
// MODE 0: relu(hidden) -> resid, rmsnorm, quant -> g_yq
// MODE 1: rmsnorm(g_resid), quant -> g_yq
// MODE 2: rmsnorm(g_resid) -> out (fp32)
template <int MODE>
static __device__ __forceinline__ void norm_body(int row,
                                                 const float* __restrict__ hid,
                                                 const float* __restrict__ nw,
                                                 const float* __restrict__ ag, int agi,
                                                 float* __restrict__ out) {
    __shared__ float red[8];
    int t = threadIdx.x, lane = t & 31, wid = t >> 5;
    size_t base = (size_t)row * HH + t * 16;
    const float* src = (MODE == 0) ? (hid + base) : (g_resid + base);

    float x[16];
    const float4* s4 = reinterpret_cast<const float4*>(src);
#pragma unroll
    for (int i = 0; i < 4; i++) {
        float4 v = s4[i];
        x[4 * i] = v.x; x[4 * i + 1] = v.y; x[4 * i + 2] = v.z; x[4 * i + 3] = v.w;
    }
    if (MODE == 0) {
#pragma unroll
        for (int i = 0; i < 16; i++) x[i] = fmaxf(x[i], 0.0f);
        float4* r4 = reinterpret_cast<float4*>(g_resid + base);
#pragma unroll
        for (int i = 0; i < 4; i++)
            r4[i] = make_float4(x[4 * i], x[4 * i + 1], x[4 * i + 2], x[4 * i + 3]);
    }
    float ss = 0.f;
#pragma unroll
    for (int i = 0; i < 16; i++) ss += x[i] * x[i];
#pragma unroll
    for (int o = 16; o; o >>= 1) ss += __shfl_xor_sync(0xffffffffu, ss, o);
    if (lane == 0) red[wid] = ss;
    __syncthreads();
    if (wid == 0) {
        float v = (lane < 8) ? red[lane] : 0.f;
#pragma unroll
        for (int o = 4; o; o >>= 1) v += __shfl_xor_sync(0xffffffffu, v, o);
        if (lane == 0) red[0] = v;
    }
    __syncthreads();
    float rs = __frsqrt_rn(red[0] * (1.0f / 4096.0f) + 1e-6f);

    float y[16];
    const float* nwp = nw + t * 16;
#pragma unroll
    for (int i = 0; i < 16; i++) y[i] = __fmul_rn(__fmul_rn(x[i], rs), nwp[i]);

    if (MODE == 2) {
        float4* o4 = reinterpret_cast<float4*>(out + base);
#pragma unroll
        for (int i = 0; i < 4; i++)
            o4[i] = make_float4(y[4 * i], y[4 * i + 1], y[4 * i + 2], y[4 * i + 3]);
    } else {
        float g = ag[agi];
        uint32_t pk[8];
        quant16(y, g, pk);
        uint4* q4 = reinterpret_cast<uint4*>(g_yq + base);
        q4[0] = make_uint4(pk[0], pk[1], pk[2], pk[3]);
        q4[1] = make_uint4(pk[4], pk[5], pk[6], pk[7]);
    }
}

template <int MODE>
__global__ void __launch_bounds__(256) k_norm(const float* __restrict__ hid,
                                              const float* __restrict__ nw,
                                              const float* __restrict__ ag, int agi,
                                              float* __restrict__ out) {
    norm_body<MODE>(blockIdx.x, hid, nw, ag, agi, out);
}

// ---------------- fused init: weight quant (blocks 0..12287) + norm0 --------
#define WQ_BLOCKS 12288
__global__ void __launch_bounds__(256) k_init(const float* __restrict__ w,
                                              const float* __restrict__ wg,
                                              const float* __restrict__ hid,
                                              const float* __restrict__ nw,
                                              const float* __restrict__ ag) {
    if (blockIdx.x < WQ_BLOCKS) {
        size_t blk  = (size_t)blockIdx.x * 256 + threadIdx.x;
        size_t base = blk * 16;
        int layer   = (int)(blk >> 20);
        float g = wg[layer];
        float x[16];
        const float4* s4 = reinterpret_cast<const float4*>(w + base);
#pragma unroll
        for (int i = 0; i < 4; i++) {
            float4 v = s4[i];
            x[4 * i] = v.x; x[4 * i + 1] = v.y; x[4 * i + 2] = v.z; x[4 * i + 3] = v.w;
        }
        uint32_t pk[8];
        quant16(x, g, pk);
        uint4* q4 = reinterpret_cast<uint4*>(g_wq + base);
        q4[0] = make_uint4(pk[0], pk[1], pk[2], pk[3]);
        q4[1] = make_uint4(pk[4], pk[5], pk[6], pk[7]);
    } else {
        norm_body<0>(blockIdx.x - WQ_BLOCKS, hid, nw, ag, 0, nullptr);
    }
}

// ------------------------- mma.sync GEMM (R9 config — best known) ------------
// z = yq @ wq^T, CTA tile 128x128, BK=64, 256 threads / 8 warps (2m x 4n),
// warp tile 64x32. 3 stages x 32KB = 96KB smem -> 2 CTAs/SM.
// Epilogue: g_resid += z * alpha.
#define GSTAGE 32768              // A 16KB + B 16KB
#define GSTAGES 3
#define GSMEM_TOTAL (GSTAGE * GSTAGES)   // 96 KB

static __device__ __forceinline__ void load_stage(uint32_t sb, int tid, int M0, int N0,
                                                  const __nv_bfloat16* __restrict__ Bp,
                                                  int s, int j) {
    uint32_t sa  = sb + (uint32_t)s * GSTAGE;
    uint32_t sbb = sa + 16384u;
    int k0 = j * 64;
    // A and B: each 128 rows x 128B (1024 x 16B chunks)
#pragma unroll
    for (int it = 0; it < 4; ++it) {
        int c = tid + it * 256;
        int row = c >> 3, kc = c & 7;
        uint32_t rel = sw128((uint32_t)(row * 128 + kc * 16));
        cp_async16(sa + rel,  g_yq + (size_t)(M0 + row) * HH + k0 + kc * 8);
        cp_async16(sbb + rel, Bp   + (size_t)(N0 + row) * HH + k0 + kc * 8);
    }
}

__global__ void __launch_bounds__(256, 2)
k_gemm(const float* __restrict__ ag, const float* __restrict__ wg, int layer) {
    extern __shared__ char smem[];
    uint32_t sb = smem_u32(smem);
    const int tid = threadIdx.x, wid = tid >> 5, lane = tid & 31;
    const int M0 = blockIdx.y * 128, N0 = blockIdx.x * 128;
    const int wm = wid & 1, wn = wid >> 1;      // 2 x 4 warp grid
    const __nv_bfloat16* Bp = g_wq + (size_t)layer * HH * HH;

    float acc[4][4][4];
#pragma unroll
    for (int i = 0; i < 4; i++)
#pragma unroll
        for (int j = 0; j < 4; j++)
#pragma unroll
            for (int k = 0; k < 4; k++) acc[i][j][k] = 0.f;

    // lane-invariant ldmatrix address pieces
    const int arow = wm * 64 + (lane & 7) + ((lane >> 3) & 1) * 8;   // + mf*16
    const int akh  = (lane >> 4) * 8;                                 // k half (0/8)
    const int brow = wn * 32 + (lane & 7) + (lane >> 4) * 8;          // + p*16
    const int bkh  = ((lane >> 3) & 1) * 8;

    // prologue: stages 0,1
#pragma unroll
    for (int j = 0; j < 2; j++) {
        load_stage(sb, tid, M0, N0, Bp, j, j);
        asm volatile("cp.async.commit_group;" ::: "memory");
    }

    // uniform: one commit per iteration (empty in tail) so wait_group 1
    // always means "stage kk's group is complete".
    for (int kk = 0; kk < 64; ++kk) {
        asm volatile("cp.async.wait_group 1;" ::: "memory");
        __syncthreads();

        int jn = kk + 2;
        if (jn < 64) load_stage(sb, tid, M0, N0, Bp, jn % GSTAGES, jn);
        asm volatile("cp.async.commit_group;" ::: "memory");

        uint32_t Ab = sb + (uint32_t)(kk % GSTAGES) * GSTAGE;
        uint32_t Bb = Ab + 16384u;
#pragma unroll
        for (int ks = 0; ks < 4; ks++) {
            uint32_t a[4][4];
#pragma unroll
            for (int mf = 0; mf < 4; mf++) {
                uint32_t addr = Ab + sw128((uint32_t)((arow + mf * 16) * 128 + (ks * 16 + akh) * 2));
                LDSM4(a[mf], addr);
            }
            uint32_t b[2][4];
#pragma unroll
            for (int p = 0; p < 2; p++) {
                uint32_t addr = Bb + sw128((uint32_t)((brow + p * 16) * 128 + (ks * 16 + bkh) * 2));
                LDSM4(b[p], addr);
            }
#pragma unroll
            for (int mf = 0; mf < 4; mf++) {
#pragma unroll
                for (int nf = 0; nf < 4; nf++)
                    MMA16816(acc[mf][nf], a[mf], b[nf >> 1][(nf & 1) * 2], b[nf >> 1][(nf & 1) * 2 + 1]);
            }
        }
    }

    // ---------------- epilogue: g_resid += acc * alpha ----------------------
    float alpha = __fdiv_rn(1.0f, __fmul_rn(ag[layer], wg[layer]));
    int qr = lane >> 2, qc = lane & 3;
#pragma unroll
    for (int mf = 0; mf < 4; mf++) {
#pragma unroll
        for (int nf = 0; nf < 4; nf++) {
            int m0 = M0 + wm * 64 + mf * 16 + qr;
            int n0 = N0 + wn * 32 + nf * 8 + 2 * qc;
            float2* p0 = reinterpret_cast<float2*>(&g_resid[(size_t)m0 * HH + n0]);
            float2 v0 = *p0;
            v0.x += __fmul_rn(acc[mf][nf][0], alpha);
            v0.y += __fmul_rn(acc[mf][nf][1], alpha);
            *p0 = v0;
            float2* p1 = reinterpret_cast<float2*>(&g_resid[(size_t)(m0 + 8) * HH + n0]);
            float2 v1 = *p1;
            v1.x += __fmul_rn(acc[mf][nf][2], alpha);
            v1.y += __fmul_rn(acc[mf][nf][3], alpha);
            *p1 = v1;
        }
    }
}

// ------------------------- launcher ------------------------------------------
extern "C" void kernel_launch(void* const* d_in, const int* in_sizes, int n_in,
                              void* d_out, int out_size) {
    const float* hid = (const float*)d_in[0];   // [8192, 4096]
    const float* nw  = (const float*)d_in[1];   // [4, 4096]
    const float* w   = (const float*)d_in[2];   // [3, 4096, 4096]
    const float* ag  = (const float*)d_in[3];   // [3]
    const float* wg  = (const float*)d_in[4];   // [3]
    float* out = (float*)d_out;

    cudaFuncSetAttribute(k_gemm, cudaFuncAttributeMaxDynamicSharedMemorySize, GSMEM_TOTAL);

    // fused: weight quant + relu/resid/rmsnorm/quant(ag[0])
    k_init<<<WQ_BLOCKS + TT, 256>>>(w, wg, hid, nw, ag);

    dim3 ggrid(HH / 128, TT / 128);  // (32, 64): N fastest for B reuse in L2
    for (int i = 0; i < 3; i++) {
        k_gemm<<<ggrid, 256, GSMEM_TOTAL>>>(ag, wg, i);
        if (i < 2)
            k_norm<1><<<TT, 256>>>(nullptr, nw + (size_t)(i + 1) * HH, ag, i + 1, nullptr);
    }
    k_norm<2><<<TT, 256>>>(nullptr, nw + (size_t)3 * HH, ag, 0, out);
}